// round 2
// baseline (speedup 1.0000x reference)
#include <cuda_runtime.h>
#include <cstdint>

#define N_NODES 8192
#define D_IN    128
#define D_OUT   128

// ---------------- device scratch (static, allocation-free) ----------------
__device__ float g_dinv[N_NODES];
__device__ float g_Bt[(size_t)D_OUT * N_NODES];              // B^T: [128][8192] K-major, tf32-rounded, dinv-scaled
__device__ float g_part[2][(size_t)N_NODES * D_OUT];         // K-split partial outputs

__device__ __forceinline__ uint32_t smem_u32(const void* p) {
    uint32_t a;
    asm("{ .reg .u64 t; cvta.to.shared.u64 t, %1; cvt.u32.u64 %0, t; }" : "=r"(a) : "l"(p));
    return a;
}
__device__ __forceinline__ void cp_async16(uint32_t dst, const void* src) {
    asm volatile("cp.async.cg.shared.global [%0], [%1], 16;" :: "r"(dst), "l"(src));
}
#define CP_COMMIT() asm volatile("cp.async.commit_group;" ::: "memory")

__device__ __forceinline__ void mma_tf32_16x8x8(float c[4], uint32_t a0, uint32_t a1, uint32_t a2, uint32_t a3,
                                                uint32_t b0, uint32_t b1) {
    asm volatile(
        "mma.sync.aligned.m16n8k8.row.col.f32.tf32.tf32.f32 "
        "{%0,%1,%2,%3}, {%4,%5,%6,%7}, {%8,%9}, {%0,%1,%2,%3};"
        : "+f"(c[0]), "+f"(c[1]), "+f"(c[2]), "+f"(c[3])
        : "r"(a0), "r"(a1), "r"(a2), "r"(a3), "r"(b0), "r"(b1));
}

// ================= kernel 1: row sums -> dinv =================
__global__ void rowsum_kernel(const float* __restrict__ A) {
    int row = blockIdx.x;
    const float4* arow = reinterpret_cast<const float4*>(A + (size_t)row * N_NODES);
    float s = 0.f;
    for (int i = threadIdx.x; i < N_NODES / 4; i += 256) {
        float4 v = __ldcs(&arow[i]);
        s += (v.x + v.y) + (v.z + v.w);
    }
    #pragma unroll
    for (int o = 16; o; o >>= 1) s += __shfl_xor_sync(0xffffffffu, s, o);
    __shared__ float ws[8];
    if ((threadIdx.x & 31) == 0) ws[threadIdx.x >> 5] = s;
    __syncthreads();
    if (threadIdx.x < 8) {
        float t = ws[threadIdx.x];
        #pragma unroll
        for (int o = 4; o; o >>= 1) t += __shfl_xor_sync(0xffu, t, o);
        if (threadIdx.x == 0) g_dinv[row] = 1.0f / (sqrtf(t) + 1e-8f);
    }
}

// ============ kernel 2: B^T[o][j] = tf32( dinv[j] * (V@W + b)[j][o] ) ============
__global__ void fc_kernel(const float* __restrict__ values, const float* __restrict__ W,
                          const float* __restrict__ bvec) {
    int tid = threadIdx.x;
    int o = tid & 127;
    int half = tid >> 7;
    int j0 = blockIdx.x * 32 + half * 16;
    float acc[16];
    #pragma unroll
    for (int i = 0; i < 16; ++i) acc[i] = 0.f;
    const float* vbase = values + (size_t)j0 * D_IN;
    for (int k = 0; k < D_IN; k += 4) {
        float w0 = W[(k + 0) * D_OUT + o];
        float w1 = W[(k + 1) * D_OUT + o];
        float w2 = W[(k + 2) * D_OUT + o];
        float w3 = W[(k + 3) * D_OUT + o];
        #pragma unroll
        for (int jj = 0; jj < 16; ++jj) {
            float4 v = *reinterpret_cast<const float4*>(vbase + jj * D_IN + k);
            acc[jj] = fmaf(v.x, w0, fmaf(v.y, w1, fmaf(v.z, w2, fmaf(v.w, w3, acc[jj]))));
        }
    }
    float bo = bvec[o];
    #pragma unroll
    for (int jj = 0; jj < 16; ++jj) {
        int j = j0 + jj;
        float y = (acc[jj] + bo) * g_dinv[j];
        uint32_t t;
        asm("cvt.rna.tf32.f32 %0, %1;" : "=r"(t) : "f"(y));
        g_Bt[(size_t)o * N_NODES + j] = __uint_as_float(t);
    }
}

// ================= kernel 3: partial = A[rows, khalf] @ B[khalf, :] =================
#define BM 128
#define BN 128
#define BK 32
#define STAGES 4
#define ROWF 40                       // BK + 8 pad floats: conflict-free (8*row + k) % 32
#define TILE_F (128 * ROWF)           // floats per operand tile
#define STAGE_F (2 * TILE_F)
#define GEMM_SMEM (STAGES * STAGE_F * 4)
#define KSPLIT 2
#define KPER (N_NODES / KSPLIT)       // 4096
#define ITERS (KPER / BK)             // 128

__device__ __forceinline__ void load_stage(int it, int buf, int tid, int row_base, size_t k0,
                                           const float* __restrict__ A, uint32_t smem_base) {
    const size_t kk = k0 + (size_t)it * BK;
    const uint32_t sbase = smem_base + (uint32_t)buf * (STAGE_F * 4);
    #pragma unroll
    for (int i = 0; i < 16; ++i) {
        int c = tid + i * 128;            // 0..2047 16B chunks
        int tile = c >> 10;               // 0: A, 1: B
        int within = c & 1023;
        int row = within >> 3;
        int h = within & 7;
        uint32_t dst = sbase + (uint32_t)tile * (TILE_F * 4) + (uint32_t)(row * (ROWF * 4) + h * 16);
        const float* src = (tile == 0)
            ? A    + (size_t)(row_base + row) * N_NODES + kk + (size_t)h * 4
            : g_Bt + (size_t)row              * N_NODES + kk + (size_t)h * 4;
        cp_async16(dst, src);
    }
}

__global__ void __launch_bounds__(128, 1)
gemm_kernel(const float* __restrict__ A) {
    extern __shared__ float smem[];
    const uint32_t smem_base = smem_u32(smem);
    const int tid = threadIdx.x;
    const int lane = tid & 31;
    const int wid = tid >> 5;
    const int wm = wid & 1;               // warp grid 2x2, warp tile 64x64
    const int wn = wid >> 1;
    const int g = lane >> 2;              // groupID
    const int tg = lane & 3;              // threadID in group
    const int row_base = blockIdx.x * BM;
    const int ksplit = blockIdx.y;
    const size_t k0 = (size_t)ksplit * KPER;

    float c[4][8][4];
    #pragma unroll
    for (int mi = 0; mi < 4; ++mi)
        #pragma unroll
        for (int ni = 0; ni < 8; ++ni)
            #pragma unroll
            for (int q = 0; q < 4; ++q) c[mi][ni][q] = 0.f;

    // prologue: stages 0..STAGES-2
    #pragma unroll
    for (int s = 0; s < STAGES - 1; ++s) {
        load_stage(s, s, tid, row_base, k0, A, smem_base);
        CP_COMMIT();
    }

    for (int it = 0; it < ITERS; ++it) {
        asm volatile("cp.async.wait_group %0;" :: "n"(STAGES - 2) : "memory");
        __syncthreads();

        int nxt = it + STAGES - 1;
        if (nxt < ITERS) load_stage(nxt, nxt & (STAGES - 1), tid, row_base, k0, A, smem_base);
        CP_COMMIT();   // always commit (possibly empty) to keep group accounting exact

        const float* As = smem + (it & (STAGES - 1)) * STAGE_F;
        const float* Bs = As + TILE_F;

        #pragma unroll
        for (int ks = 0; ks < 4; ++ks) {
            const int k = ks * 8 + tg;
            uint32_t a[4][4], b[8][2];
            #pragma unroll
            for (int mi = 0; mi < 4; ++mi) {
                const int r = wm * 64 + mi * 16 + g;
                a[mi][0] = __float_as_uint(As[r * ROWF + k]);
                a[mi][1] = __float_as_uint(As[(r + 8) * ROWF + k]);
                a[mi][2] = __float_as_uint(As[r * ROWF + k + 4]);
                a[mi][3] = __float_as_uint(As[(r + 8) * ROWF + k + 4]);
            }
            #pragma unroll
            for (int ni = 0; ni < 8; ++ni) {
                const int n = wn * 64 + ni * 8 + g;
                b[ni][0] = __float_as_uint(Bs[n * ROWF + k]);
                b[ni][1] = __float_as_uint(Bs[n * ROWF + k + 4]);
            }
            #pragma unroll
            for (int mi = 0; mi < 4; ++mi)
                #pragma unroll
                for (int ni = 0; ni < 8; ++ni)
                    mma_tf32_16x8x8(c[mi][ni], a[mi][0], a[mi][1], a[mi][2], a[mi][3],
                                    b[ni][0], b[ni][1]);
        }
    }

    // epilogue: write K-split partials (unscaled)
    float* P = g_part[ksplit];
    #pragma unroll
    for (int mi = 0; mi < 4; ++mi) {
        const int r0 = row_base + wm * 64 + mi * 16 + g;
        #pragma unroll
        for (int ni = 0; ni < 8; ++ni) {
            const int col = wn * 64 + ni * 8 + 2 * tg;
            float2 lo = make_float2(c[mi][ni][0], c[mi][ni][1]);
            float2 hi = make_float2(c[mi][ni][2], c[mi][ni][3]);
            *reinterpret_cast<float2*>(P + (size_t)r0 * D_OUT + col) = lo;
            *reinterpret_cast<float2*>(P + (size_t)(r0 + 8) * D_OUT + col) = hi;
        }
    }
}

// ================= kernel 4: out = dinv[row] * (part0 + part1) =================
__global__ void reduce_kernel(float* __restrict__ out) {
    int i = blockIdx.x * 256 + threadIdx.x;            // over 1M/4 float4s
    const float4 p0 = reinterpret_cast<const float4*>(g_part[0])[i];
    const float4 p1 = reinterpret_cast<const float4*>(g_part[1])[i];
    int row = (i * 4) >> 7;                            // D_OUT = 128
    float s = g_dinv[row];
    float4 r;
    r.x = s * (p0.x + p1.x);
    r.y = s * (p0.y + p1.y);
    r.z = s * (p0.z + p1.z);
    r.w = s * (p0.w + p1.w);
    reinterpret_cast<float4*>(out)[i] = r;
}

// ================= launch =================
extern "C" void kernel_launch(void* const* d_in, const int* in_sizes, int n_in,
                              void* d_out, int out_size) {
    const float* values = (const float*)d_in[0];
    const float* A      = (const float*)d_in[1];
    const float* W      = (const float*)d_in[2];
    const float* b      = (const float*)d_in[3];
    float* out = (float*)d_out;

    rowsum_kernel<<<N_NODES, 256>>>(A);
    fc_kernel<<<N_NODES / 32, 256>>>(values, W, b);
    cudaFuncSetAttribute(gemm_kernel, cudaFuncAttributeMaxDynamicSharedMemorySize, GEMM_SMEM);
    gemm_kernel<<<dim3(N_NODES / BM, KSPLIT), 128, GEMM_SMEM>>>(A);
    reduce_kernel<<<(N_NODES * D_OUT / 4) / 256, 256>>>(out);
}

// round 3
// speedup vs baseline: 1.1086x; 1.1086x over previous
#include <cuda_runtime.h>
#include <cstdint>

#define N_NODES 8192
#define D_IN    128
#define D_OUT   128

// ---------------- device scratch (static, allocation-free) ----------------
__device__ float g_dinv[N_NODES];
__device__ float g_Bt[(size_t)D_OUT * N_NODES];              // B^T: [128][8192] K-major, tf32-rounded, dinv-scaled
__device__ float g_part[2][(size_t)N_NODES * D_OUT];         // K-split partial outputs

__device__ __forceinline__ uint32_t smem_u32(const void* p) {
    uint32_t a;
    asm("{ .reg .u64 t; cvta.to.shared.u64 t, %1; cvt.u32.u64 %0, t; }" : "=r"(a) : "l"(p));
    return a;
}
__device__ __forceinline__ void cp_async16(uint32_t dst, const void* src) {
    asm volatile("cp.async.cg.shared.global [%0], [%1], 16;" :: "r"(dst), "l"(src));
}
#define CP_COMMIT() asm volatile("cp.async.commit_group;" ::: "memory")

__device__ __forceinline__ void mma_tf32_16x8x8(float c[4], uint32_t a0, uint32_t a1, uint32_t a2, uint32_t a3,
                                                uint32_t b0, uint32_t b1) {
    asm volatile(
        "mma.sync.aligned.m16n8k8.row.col.f32.tf32.tf32.f32 "
        "{%0,%1,%2,%3}, {%4,%5,%6,%7}, {%8,%9}, {%0,%1,%2,%3};"
        : "+f"(c[0]), "+f"(c[1]), "+f"(c[2]), "+f"(c[3])
        : "r"(a0), "r"(a1), "r"(a2), "r"(a3), "r"(b0), "r"(b1));
}
__device__ __forceinline__ void ldsm_x4(uint32_t r[4], uint32_t addr) {
    asm volatile("ldmatrix.sync.aligned.m8n8.x4.shared.b16 {%0,%1,%2,%3}, [%4];"
        : "=r"(r[0]), "=r"(r[1]), "=r"(r[2]), "=r"(r[3]) : "r"(addr));
}
__device__ __forceinline__ uint32_t swz(uint32_t off) { return off ^ ((off >> 3) & 0x70); }

// ================= kernel 1: row sums -> dinv =================
__global__ void rowsum_kernel(const float* __restrict__ A) {
    int row = blockIdx.x;
    const float4* arow = reinterpret_cast<const float4*>(A + (size_t)row * N_NODES);
    float s = 0.f;
    for (int i = threadIdx.x; i < N_NODES / 4; i += 256) {
        float4 v = __ldcs(&arow[i]);
        s += (v.x + v.y) + (v.z + v.w);
    }
    #pragma unroll
    for (int o = 16; o; o >>= 1) s += __shfl_xor_sync(0xffffffffu, s, o);
    __shared__ float ws[8];
    if ((threadIdx.x & 31) == 0) ws[threadIdx.x >> 5] = s;
    __syncthreads();
    if (threadIdx.x < 8) {
        float t = ws[threadIdx.x];
        #pragma unroll
        for (int o = 4; o; o >>= 1) t += __shfl_xor_sync(0xffu, t, o);
        if (threadIdx.x == 0) g_dinv[row] = 1.0f / (sqrtf(t) + 1e-8f);
    }
}

// ============ kernel 2: B^T[o][j] = tf32( dinv[j] * (V@W + b)[j][o] ) ============
__global__ void fc_kernel(const float* __restrict__ values, const float* __restrict__ W,
                          const float* __restrict__ bvec) {
    int tid = threadIdx.x;
    int o = tid & 127;
    int half = tid >> 7;
    int j0 = blockIdx.x * 32 + half * 16;
    float acc[16];
    #pragma unroll
    for (int i = 0; i < 16; ++i) acc[i] = 0.f;
    const float* vbase = values + (size_t)j0 * D_IN;
    for (int k = 0; k < D_IN; k += 4) {
        float w0 = W[(k + 0) * D_OUT + o];
        float w1 = W[(k + 1) * D_OUT + o];
        float w2 = W[(k + 2) * D_OUT + o];
        float w3 = W[(k + 3) * D_OUT + o];
        #pragma unroll
        for (int jj = 0; jj < 16; ++jj) {
            float4 v = *reinterpret_cast<const float4*>(vbase + jj * D_IN + k);
            acc[jj] = fmaf(v.x, w0, fmaf(v.y, w1, fmaf(v.z, w2, fmaf(v.w, w3, acc[jj]))));
        }
    }
    float bo = bvec[o];
    #pragma unroll
    for (int jj = 0; jj < 16; ++jj) {
        int j = j0 + jj;
        float y = (acc[jj] + bo) * g_dinv[j];
        uint32_t t;
        asm("cvt.rna.tf32.f32 %0, %1;" : "=r"(t) : "f"(y));
        g_Bt[(size_t)o * N_NODES + j] = __uint_as_float(t);
    }
}

// ================= kernel 3: partial = A[rows, khalf] @ B[khalf, :] =================
// CTA tile 128x128, BK=32, 8 warps (2m x 4n), warp tile 64x32, ldmatrix fragments.
#define BM 128
#define BK 32
#define STAGES 4
#define A_TILE_BYTES 16384            // 128 rows x 128B (32 tf32)
#define STAGE_BYTES 32768             // A + B
#define GEMM_SMEM (STAGES * STAGE_BYTES)
#define KSPLIT 2
#define KPER (N_NODES / KSPLIT)       // 4096
#define ITERS (KPER / BK)             // 128

__device__ __forceinline__ void load_stage(int it, int buf, int tid, int row_base, size_t k0,
                                           const float* __restrict__ A, uint32_t smem_base) {
    const size_t kk = k0 + (size_t)it * BK;
    const uint32_t sbase = smem_base + (uint32_t)buf * STAGE_BYTES;
    #pragma unroll
    for (int i = 0; i < 8; ++i) {
        int c = tid + i * 256;            // 0..2047 16B chunks
        int tile = c >> 10;               // 0: A, 1: B
        int within = c & 1023;
        int row = within >> 3;            // 0..127
        int h = within & 7;               // 16B chunk in 128B row
        uint32_t dst = sbase + (uint32_t)tile * A_TILE_BYTES + swz((uint32_t)(row * 128 + h * 16));
        const float* src = (tile == 0)
            ? A    + (size_t)(row_base + row) * N_NODES + kk + (size_t)h * 4
            : g_Bt + (size_t)row              * N_NODES + kk + (size_t)h * 4;
        cp_async16(dst, src);
    }
}

__global__ void __launch_bounds__(256, 1)
gemm_kernel(const float* __restrict__ A) {
    extern __shared__ float smem[];
    const uint32_t smem_base = smem_u32(smem);
    const int tid = threadIdx.x;
    const int lane = tid & 31;
    const int wid = tid >> 5;
    const int wm = wid & 1;               // 2 warps in m
    const int wn = wid >> 1;              // 4 warps in n
    const int g  = lane >> 2;
    const int tg = lane & 3;
    const int row_base = blockIdx.x * BM;
    const int ksplit = blockIdx.y;
    const size_t k0 = (size_t)ksplit * KPER;

    // ldmatrix per-lane constants
    const int aRow = wm * 64 + ((lane >> 3) & 1) * 8 + (lane & 7);   // + mi*16
    const int aKb  = (lane >> 4) * 16;                               // + ks*32
    const int bRow = wn * 32 + (lane >> 4) * 8 + (lane & 7);         // + p*16
    const int bKb  = ((lane >> 3) & 1) * 16;                         // + ks*32

    float c[4][4][4];
    #pragma unroll
    for (int mi = 0; mi < 4; ++mi)
        #pragma unroll
        for (int ni = 0; ni < 4; ++ni)
            #pragma unroll
            for (int q = 0; q < 4; ++q) c[mi][ni][q] = 0.f;

    #pragma unroll
    for (int s = 0; s < STAGES - 1; ++s) {
        load_stage(s, s, tid, row_base, k0, A, smem_base);
        CP_COMMIT();
    }

    for (int it = 0; it < ITERS; ++it) {
        asm volatile("cp.async.wait_group %0;" :: "n"(STAGES - 2) : "memory");
        __syncthreads();

        int nxt = it + STAGES - 1;
        if (nxt < ITERS) load_stage(nxt, nxt & (STAGES - 1), tid, row_base, k0, A, smem_base);
        CP_COMMIT();

        const uint32_t smA = smem_base + (uint32_t)(it & (STAGES - 1)) * STAGE_BYTES;
        const uint32_t smB = smA + A_TILE_BYTES;

        #pragma unroll
        for (int ks = 0; ks < 4; ++ks) {
            uint32_t a[4][4], b[2][4];
            #pragma unroll
            for (int mi = 0; mi < 4; ++mi)
                ldsm_x4(a[mi], smA + swz((uint32_t)((aRow + mi * 16) * 128 + ks * 32 + aKb)));
            #pragma unroll
            for (int p = 0; p < 2; ++p)
                ldsm_x4(b[p], smB + swz((uint32_t)((bRow + p * 16) * 128 + ks * 32 + bKb)));
            #pragma unroll
            for (int mi = 0; mi < 4; ++mi) {
                #pragma unroll
                for (int ni = 0; ni < 4; ++ni) {
                    mma_tf32_16x8x8(c[mi][ni], a[mi][0], a[mi][1], a[mi][2], a[mi][3],
                                    b[ni >> 1][(ni & 1) * 2], b[ni >> 1][(ni & 1) * 2 + 1]);
                }
            }
        }
    }

    // epilogue: write K-split partials (unscaled)
    float* P = g_part[ksplit];
    #pragma unroll
    for (int mi = 0; mi < 4; ++mi) {
        const int r0 = row_base + wm * 64 + mi * 16 + g;
        #pragma unroll
        for (int ni = 0; ni < 4; ++ni) {
            const int col = wn * 32 + ni * 8 + 2 * tg;
            float2 lo = make_float2(c[mi][ni][0], c[mi][ni][1]);
            float2 hi = make_float2(c[mi][ni][2], c[mi][ni][3]);
            *reinterpret_cast<float2*>(P + (size_t)r0 * D_OUT + col) = lo;
            *reinterpret_cast<float2*>(P + (size_t)(r0 + 8) * D_OUT + col) = hi;
        }
    }
}

// ================= kernel 4: out = dinv[row] * (part0 + part1) =================
__global__ void reduce_kernel(float* __restrict__ out) {
    int i = blockIdx.x * 256 + threadIdx.x;
    const float4 p0 = reinterpret_cast<const float4*>(g_part[0])[i];
    const float4 p1 = reinterpret_cast<const float4*>(g_part[1])[i];
    int row = (i * 4) >> 7;
    float s = g_dinv[row];
    float4 r;
    r.x = s * (p0.x + p1.x);
    r.y = s * (p0.y + p1.y);
    r.z = s * (p0.z + p1.z);
    r.w = s * (p0.w + p1.w);
    reinterpret_cast<float4*>(out)[i] = r;
}

// ================= launch =================
extern "C" void kernel_launch(void* const* d_in, const int* in_sizes, int n_in,
                              void* d_out, int out_size) {
    const float* values = (const float*)d_in[0];
    const float* A      = (const float*)d_in[1];
    const float* W      = (const float*)d_in[2];
    const float* b      = (const float*)d_in[3];
    float* out = (float*)d_out;

    rowsum_kernel<<<N_NODES, 256>>>(A);
    fc_kernel<<<N_NODES / 32, 256>>>(values, W, b);
    cudaFuncSetAttribute(gemm_kernel, cudaFuncAttributeMaxDynamicSharedMemorySize, GEMM_SMEM);
    gemm_kernel<<<dim3(N_NODES / BM, KSPLIT), 256, GEMM_SMEM>>>(A);
    reduce_kernel<<<(N_NODES * D_OUT / 4) / 256, 256>>>(out);
}

// round 4
// speedup vs baseline: 1.1540x; 1.0409x over previous
#include <cuda_runtime.h>
#include <cstdint>

#define N_NODES 8192
#define D_IN    128
#define D_OUT   128

// ---------------- device scratch (static, allocation-free) ----------------
__device__ float g_dinv[N_NODES];
__device__ float g_Bt[(size_t)D_OUT * N_NODES];              // B^T: [128][8192] K-major, tf32-rounded, dinv-scaled
__device__ float g_part[2][(size_t)N_NODES * D_OUT];         // K-split partial outputs

__device__ __forceinline__ uint32_t smem_u32(const void* p) {
    uint32_t a;
    asm("{ .reg .u64 t; cvta.to.shared.u64 t, %1; cvt.u32.u64 %0, t; }" : "=r"(a) : "l"(p));
    return a;
}
__device__ __forceinline__ void cp_async16(uint32_t dst, const void* src) {
    asm volatile("cp.async.cg.shared.global [%0], [%1], 16;" :: "r"(dst), "l"(src));
}
#define CP_COMMIT() asm volatile("cp.async.commit_group;" ::: "memory")

__device__ __forceinline__ void mma_tf32_16x8x8(float c[4], uint32_t a0, uint32_t a1, uint32_t a2, uint32_t a3,
                                                uint32_t b0, uint32_t b1) {
    asm volatile(
        "mma.sync.aligned.m16n8k8.row.col.f32.tf32.tf32.f32 "
        "{%0,%1,%2,%3}, {%4,%5,%6,%7}, {%8,%9}, {%0,%1,%2,%3};"
        : "+f"(c[0]), "+f"(c[1]), "+f"(c[2]), "+f"(c[3])
        : "r"(a0), "r"(a1), "r"(a2), "r"(a3), "r"(b0), "r"(b1));
}
__device__ __forceinline__ void ldsm_x4(uint32_t r[4], uint32_t addr) {
    asm volatile("ldmatrix.sync.aligned.m8n8.x4.shared.b16 {%0,%1,%2,%3}, [%4];"
        : "=r"(r[0]), "=r"(r[1]), "=r"(r[2]), "=r"(r[3]) : "r"(addr));
}
__device__ __forceinline__ uint32_t swz(uint32_t off) { return off ^ ((off >> 3) & 0x70); }

// ================= kernel 1: row sums -> dinv =================
__global__ void rowsum_kernel(const float* __restrict__ A) {
    int row = blockIdx.x;
    const float4* arow = reinterpret_cast<const float4*>(A + (size_t)row * N_NODES);
    // 2048 float4s per row, 256 threads -> 8 fully independent loads per thread
    float4 v[8];
    #pragma unroll
    for (int i = 0; i < 8; ++i) v[i] = __ldcs(&arow[threadIdx.x + i * 256]);
    float s = 0.f;
    #pragma unroll
    for (int i = 0; i < 8; ++i) s += (v[i].x + v[i].y) + (v[i].z + v[i].w);
    #pragma unroll
    for (int o = 16; o; o >>= 1) s += __shfl_xor_sync(0xffffffffu, s, o);
    __shared__ float ws[8];
    if ((threadIdx.x & 31) == 0) ws[threadIdx.x >> 5] = s;
    __syncthreads();
    if (threadIdx.x < 8) {
        float t = ws[threadIdx.x];
        #pragma unroll
        for (int o = 4; o; o >>= 1) t += __shfl_xor_sync(0xffu, t, o);
        if (threadIdx.x == 0) g_dinv[row] = 1.0f / (sqrtf(t) + 1e-8f);
    }
}

// ============ kernel 2: B^T[o][j] = tf32( dinv[j] * (V@W + b)[j][o] ) ============
__global__ void fc_kernel(const float* __restrict__ values, const float* __restrict__ W,
                          const float* __restrict__ bvec) {
    int tid = threadIdx.x;
    int o = tid & 127;
    int half = tid >> 7;
    int j0 = blockIdx.x * 32 + half * 16;
    float acc[16];
    #pragma unroll
    for (int i = 0; i < 16; ++i) acc[i] = 0.f;
    const float* vbase = values + (size_t)j0 * D_IN;
    for (int k = 0; k < D_IN; k += 4) {
        float w0 = W[(k + 0) * D_OUT + o];
        float w1 = W[(k + 1) * D_OUT + o];
        float w2 = W[(k + 2) * D_OUT + o];
        float w3 = W[(k + 3) * D_OUT + o];
        #pragma unroll
        for (int jj = 0; jj < 16; ++jj) {
            float4 v = *reinterpret_cast<const float4*>(vbase + jj * D_IN + k);
            acc[jj] = fmaf(v.x, w0, fmaf(v.y, w1, fmaf(v.z, w2, fmaf(v.w, w3, acc[jj]))));
        }
    }
    float bo = bvec[o];
    #pragma unroll
    for (int jj = 0; jj < 16; ++jj) {
        int j = j0 + jj;
        float y = (acc[jj] + bo) * g_dinv[j];
        uint32_t t;
        asm("cvt.rna.tf32.f32 %0, %1;" : "=r"(t) : "f"(y));
        g_Bt[(size_t)o * N_NODES + j] = __uint_as_float(t);
    }
}

// ================= kernel 3: partial = A[rows, khalf] @ B[khalf, :] =================
// CTA tile 128x128, BK=32, 8 warps in 2m x 2n x 2k grid; warp tile 64x64 over half-BK.
// k-half accumulator pairs merged through smem in the epilogue.
#define BM 128
#define BK 32
#define STAGES 4
#define A_TILE_BYTES 16384            // 128 rows x 128B (32 tf32)
#define STAGE_BYTES 32768             // A + B
#define GEMM_SMEM (STAGES * STAGE_BYTES)
#define KSPLIT 2
#define KPER (N_NODES / KSPLIT)       // 4096
#define ITERS (KPER / BK)             // 128

__device__ __forceinline__ void load_stage(int it, int buf, int tid, int row_base, size_t k0,
                                           const float* __restrict__ A, uint32_t smem_base) {
    const size_t kk = k0 + (size_t)it * BK;
    const uint32_t sbase = smem_base + (uint32_t)buf * STAGE_BYTES;
    #pragma unroll
    for (int i = 0; i < 8; ++i) {
        int c = tid + i * 256;            // 0..2047 16B chunks
        int tile = c >> 10;               // 0: A, 1: B
        int within = c & 1023;
        int row = within >> 3;            // 0..127
        int h = within & 7;               // 16B chunk in 128B row
        uint32_t dst = sbase + (uint32_t)tile * A_TILE_BYTES + swz((uint32_t)(row * 128 + h * 16));
        const float* src = (tile == 0)
            ? A    + (size_t)(row_base + row) * N_NODES + kk + (size_t)h * 4
            : g_Bt + (size_t)row              * N_NODES + kk + (size_t)h * 4;
        cp_async16(dst, src);
    }
}

__global__ void __launch_bounds__(256, 1)
gemm_kernel(const float* __restrict__ A) {
    extern __shared__ float smem[];
    const uint32_t smem_base = smem_u32(smem);
    const int tid = threadIdx.x;
    const int lane = tid & 31;
    const int wid = tid >> 5;
    const int wm = wid & 1;               // 2 warps in m (64 rows each)
    const int wn = (wid >> 1) & 1;        // 2 warps in n (64 cols each)
    const int kh = wid >> 2;              // 2 warps in k (16-wide halves of BK)
    const int g  = lane >> 2;
    const int tg = lane & 3;
    const int row_base = blockIdx.x * BM;
    const int ksplit = blockIdx.y;
    const size_t k0 = (size_t)ksplit * KPER;

    // ldmatrix per-lane address components (byte offsets within 128B rows)
    const int aRow = wm * 64 + ((lane >> 3) & 1) * 8 + (lane & 7);   // + mi*16
    const int aKb  = (lane >> 4) * 16;                               // 16B k-subchunk
    const int bRowL = wn * 64 + (lane >> 4) * 8 + (lane & 7);        // + cb*16
    const int bKb  = ((lane >> 3) & 1) * 16;
    const int kOfs = kh * 64;                                        // k-half byte offset

    float c[4][8][4];
    #pragma unroll
    for (int mi = 0; mi < 4; ++mi)
        #pragma unroll
        for (int ni = 0; ni < 8; ++ni)
            #pragma unroll
            for (int q = 0; q < 4; ++q) c[mi][ni][q] = 0.f;

    #pragma unroll
    for (int s = 0; s < STAGES - 1; ++s) {
        load_stage(s, s, tid, row_base, k0, A, smem_base);
        CP_COMMIT();
    }

    for (int it = 0; it < ITERS; ++it) {
        asm volatile("cp.async.wait_group %0;" :: "n"(STAGES - 2) : "memory");
        __syncthreads();

        int nxt = it + STAGES - 1;
        if (nxt < ITERS) load_stage(nxt, nxt & (STAGES - 1), tid, row_base, k0, A, smem_base);
        CP_COMMIT();

        const uint32_t smA = smem_base + (uint32_t)(it & (STAGES - 1)) * STAGE_BYTES;
        const uint32_t smB = smA + A_TILE_BYTES;

        #pragma unroll
        for (int ks = 0; ks < 2; ++ks) {
            const uint32_t kb = (uint32_t)(kOfs + ks * 32);
            uint32_t a[4][4], b[4][4];
            #pragma unroll
            for (int mi = 0; mi < 4; ++mi)
                ldsm_x4(a[mi], smA + swz((uint32_t)((aRow + mi * 16) * 128) + kb + aKb));
            #pragma unroll
            for (int cb = 0; cb < 4; ++cb)
                ldsm_x4(b[cb], smB + swz((uint32_t)((bRowL + cb * 16) * 128) + kb + bKb));
            #pragma unroll
            for (int mi = 0; mi < 4; ++mi) {
                #pragma unroll
                for (int ni = 0; ni < 8; ++ni) {
                    mma_tf32_16x8x8(c[mi][ni], a[mi][0], a[mi][1], a[mi][2], a[mi][3],
                                    b[ni >> 1][(ni & 1) * 2], b[ni >> 1][(ni & 1) * 2 + 1]);
                }
            }
        }
    }

    // ---- epilogue: merge k-half partials through smem, then store ----
    __syncthreads();   // stage buffers are dead; reuse for merge
    const uint32_t pairBase = smem_base + (uint32_t)(wid & 3) * 16384u;
    if (kh == 1) {
        #pragma unroll
        for (int mi = 0; mi < 4; ++mi)
            #pragma unroll
            for (int ni = 0; ni < 8; ++ni) {
                uint32_t off = pairBase + (uint32_t)(((mi * 8 + ni) * 32 + lane) * 16);
                asm volatile("st.shared.v4.b32 [%0], {%1,%2,%3,%4};" :: "r"(off),
                    "r"(__float_as_uint(c[mi][ni][0])), "r"(__float_as_uint(c[mi][ni][1])),
                    "r"(__float_as_uint(c[mi][ni][2])), "r"(__float_as_uint(c[mi][ni][3])) : "memory");
            }
    }
    __syncthreads();
    if (kh == 0) {
        float* P = g_part[ksplit];
        #pragma unroll
        for (int mi = 0; mi < 4; ++mi) {
            const int r0 = row_base + wm * 64 + mi * 16 + g;
            #pragma unroll
            for (int ni = 0; ni < 8; ++ni) {
                uint32_t off = pairBase + (uint32_t)(((mi * 8 + ni) * 32 + lane) * 16);
                float4 p;
                asm volatile("ld.shared.v4.f32 {%0,%1,%2,%3}, [%4];"
                    : "=f"(p.x), "=f"(p.y), "=f"(p.z), "=f"(p.w) : "r"(off));
                const int col = wn * 64 + ni * 8 + 2 * tg;
                float2 lo = make_float2(c[mi][ni][0] + p.x, c[mi][ni][1] + p.y);
                float2 hi = make_float2(c[mi][ni][2] + p.z, c[mi][ni][3] + p.w);
                *reinterpret_cast<float2*>(P + (size_t)r0 * D_OUT + col) = lo;
                *reinterpret_cast<float2*>(P + (size_t)(r0 + 8) * D_OUT + col) = hi;
            }
        }
    }
}

// ================= kernel 4: out = dinv[row] * (part0 + part1) =================
__global__ void reduce_kernel(float* __restrict__ out) {
    int i = blockIdx.x * 256 + threadIdx.x;
    const float4 p0 = reinterpret_cast<const float4*>(g_part[0])[i];
    const float4 p1 = reinterpret_cast<const float4*>(g_part[1])[i];
    int row = (i * 4) >> 7;
    float s = g_dinv[row];
    float4 r;
    r.x = s * (p0.x + p1.x);
    r.y = s * (p0.y + p1.y);
    r.z = s * (p0.z + p1.z);
    r.w = s * (p0.w + p1.w);
    reinterpret_cast<float4*>(out)[i] = r;
}

// ================= launch =================
extern "C" void kernel_launch(void* const* d_in, const int* in_sizes, int n_in,
                              void* d_out, int out_size) {
    const float* values = (const float*)d_in[0];
    const float* A      = (const float*)d_in[1];
    const float* W      = (const float*)d_in[2];
    const float* b      = (const float*)d_in[3];
    float* out = (float*)d_out;

    rowsum_kernel<<<N_NODES, 256>>>(A);
    fc_kernel<<<N_NODES / 32, 256>>>(values, W, b);
    cudaFuncSetAttribute(gemm_kernel, cudaFuncAttributeMaxDynamicSharedMemorySize, GEMM_SMEM);
    gemm_kernel<<<dim3(N_NODES / BM, KSPLIT), 256, GEMM_SMEM>>>(A);
    reduce_kernel<<<(N_NODES * D_OUT / 4) / 256, 256>>>(out);
}

// round 5
// speedup vs baseline: 1.2941x; 1.1215x over previous
#include <cuda_runtime.h>
#include <cuda_fp16.h>
#include <cstdint>

#define N_NODES 8192
#define D_IN    128
#define D_OUT   128

// ---------------- device scratch (static, allocation-free) ----------------
__device__ float  g_dinv[N_NODES];
__device__ __half g_Ah[(size_t)N_NODES * N_NODES];     // fp16 copy of A (128 MB)
__device__ __half g_Bh[(size_t)D_OUT * N_NODES];       // B^T: [128][8192] K-major fp16, dinv-scaled
__device__ float  g_part[2][(size_t)N_NODES * D_OUT];  // K-split partial outputs

__device__ __forceinline__ uint32_t smem_u32(const void* p) {
    uint32_t a;
    asm("{ .reg .u64 t; cvta.to.shared.u64 t, %1; cvt.u32.u64 %0, t; }" : "=r"(a) : "l"(p));
    return a;
}
__device__ __forceinline__ void cp_async16(uint32_t dst, const void* src) {
    asm volatile("cp.async.cg.shared.global [%0], [%1], 16;" :: "r"(dst), "l"(src));
}
#define CP_COMMIT() asm volatile("cp.async.commit_group;" ::: "memory")

__device__ __forceinline__ uint32_t pack_h2(float lo, float hi) {
    uint32_t r;
    asm("cvt.rn.f16x2.f32 %0, %1, %2;" : "=r"(r) : "f"(hi), "f"(lo));
    return r;
}
__device__ __forceinline__ void mma_f16_16x8x16(float c[4], uint32_t a0, uint32_t a1, uint32_t a2, uint32_t a3,
                                                uint32_t b0, uint32_t b1) {
    asm volatile(
        "mma.sync.aligned.m16n8k16.row.col.f32.f16.f16.f32 "
        "{%0,%1,%2,%3}, {%4,%5,%6,%7}, {%8,%9}, {%0,%1,%2,%3};"
        : "+f"(c[0]), "+f"(c[1]), "+f"(c[2]), "+f"(c[3])
        : "r"(a0), "r"(a1), "r"(a2), "r"(a3), "r"(b0), "r"(b1));
}
__device__ __forceinline__ void ldsm_x4(uint32_t r[4], uint32_t addr) {
    asm volatile("ldmatrix.sync.aligned.m8n8.x4.shared.b16 {%0,%1,%2,%3}, [%4];"
        : "=r"(r[0]), "=r"(r[1]), "=r"(r[2]), "=r"(r[3]) : "r"(addr));
}

// ================= kernel 1: row sums -> dinv, plus A -> fp16 =================
__global__ void rowsum_convert_kernel(const float* __restrict__ A) {
    int row = blockIdx.x;
    const float4* arow = reinterpret_cast<const float4*>(A + (size_t)row * N_NODES);
    uint4* dst = reinterpret_cast<uint4*>(g_Ah + (size_t)row * N_NODES);
    float s = 0.f;
    #pragma unroll
    for (int i = 0; i < 4; ++i) {
        int c = threadIdx.x + i * 256;
        float4 a = __ldcs(&arow[2 * c]);
        float4 b = __ldcs(&arow[2 * c + 1]);
        s += ((a.x + a.y) + (a.z + a.w)) + ((b.x + b.y) + (b.z + b.w));
        uint4 u;
        u.x = pack_h2(a.x, a.y);
        u.y = pack_h2(a.z, a.w);
        u.z = pack_h2(b.x, b.y);
        u.w = pack_h2(b.z, b.w);
        dst[c] = u;
    }
    #pragma unroll
    for (int o = 16; o; o >>= 1) s += __shfl_xor_sync(0xffffffffu, s, o);
    __shared__ float ws[8];
    if ((threadIdx.x & 31) == 0) ws[threadIdx.x >> 5] = s;
    __syncthreads();
    if (threadIdx.x < 8) {
        float t = ws[threadIdx.x];
        #pragma unroll
        for (int o = 4; o; o >>= 1) t += __shfl_xor_sync(0xffu, t, o);
        if (threadIdx.x == 0) g_dinv[row] = 1.0f / (sqrtf(t) + 1e-8f);
    }
}

// ============ kernel 2: B^T[o][j] = fp16( dinv[j] * (V@W + b)[j][o] ) ============
__global__ void fc_kernel(const float* __restrict__ values, const float* __restrict__ W,
                          const float* __restrict__ bvec) {
    int tid = threadIdx.x;
    int o = tid & 127;
    int half_idx = tid >> 7;
    int j0 = blockIdx.x * 32 + half_idx * 16;
    float acc[16];
    #pragma unroll
    for (int i = 0; i < 16; ++i) acc[i] = 0.f;
    const float* vbase = values + (size_t)j0 * D_IN;
    for (int k = 0; k < D_IN; k += 4) {
        float w0 = W[(k + 0) * D_OUT + o];
        float w1 = W[(k + 1) * D_OUT + o];
        float w2 = W[(k + 2) * D_OUT + o];
        float w3 = W[(k + 3) * D_OUT + o];
        #pragma unroll
        for (int jj = 0; jj < 16; ++jj) {
            float4 v = *reinterpret_cast<const float4*>(vbase + jj * D_IN + k);
            acc[jj] = fmaf(v.x, w0, fmaf(v.y, w1, fmaf(v.z, w2, fmaf(v.w, w3, acc[jj]))));
        }
    }
    float bo = bvec[o];
    uint32_t packed[8];
    #pragma unroll
    for (int p = 0; p < 8; ++p) {
        float y0 = (acc[2 * p]     + bo) * g_dinv[j0 + 2 * p];
        float y1 = (acc[2 * p + 1] + bo) * g_dinv[j0 + 2 * p + 1];
        packed[p] = pack_h2(y0, y1);
    }
    uint4* dst = reinterpret_cast<uint4*>(g_Bh + (size_t)o * N_NODES + j0);
    dst[0] = make_uint4(packed[0], packed[1], packed[2], packed[3]);
    dst[1] = make_uint4(packed[4], packed[5], packed[6], packed[7]);
}

// ================= kernel 3: partial = A[rows, khalf] @ B[khalf, :] (fp16 MMA) =================
// CTA tile 128x128, BK=32, 8 warps in 2m x 2n x 2k grid; warp tile 64x64 over a k16 half.
#define BM 128
#define BK 32
#define STAGES 4
#define PITCH 80                      // 64B data + 16B pad per tile row -> conflict-free ldmatrix
#define A_TILE_BYTES (128 * PITCH)    // 10240
#define STAGE_BYTES (2 * A_TILE_BYTES)
#define GEMM_SMEM (STAGES * STAGE_BYTES)
#define KSPLIT 2
#define KPER (N_NODES / KSPLIT)       // 4096
#define ITERS (KPER / BK)             // 128

__device__ __forceinline__ void load_stage(int it, int buf, int tid, int row_base, size_t k0,
                                           uint32_t smem_base) {
    const size_t kk = k0 + (size_t)it * BK;      // in halves
    const uint32_t sbase = smem_base + (uint32_t)buf * STAGE_BYTES;
    #pragma unroll
    for (int i = 0; i < 4; ++i) {
        int c = tid + i * 256;            // 0..1023 16B chunks
        int tile = c >> 9;                // 0: A, 1: B
        int within = c & 511;
        int row = within >> 2;            // 0..127
        int h = within & 3;               // 16B chunk within 64B row
        uint32_t dst = sbase + (uint32_t)tile * A_TILE_BYTES + (uint32_t)(row * PITCH + h * 16);
        const __half* src = (tile == 0)
            ? g_Ah + (size_t)(row_base + row) * N_NODES + kk + (size_t)h * 8
            : g_Bh + (size_t)row              * N_NODES + kk + (size_t)h * 8;
        cp_async16(dst, src);
    }
}

__global__ void __launch_bounds__(256, 1)
gemm_kernel() {
    extern __shared__ float smem[];
    const uint32_t smem_base = smem_u32(smem);
    const int tid = threadIdx.x;
    const int lane = tid & 31;
    const int wid = tid >> 5;
    const int wm = wid & 1;               // 2 warps in m (64 rows)
    const int wn = (wid >> 1) & 1;        // 2 warps in n (64 cols)
    const int kh = wid >> 2;              // 2 warps in k (k16 halves of BK=32)
    const int g  = lane >> 2;
    const int tg = lane & 3;
    const int row_base = blockIdx.x * BM;
    const int ksplit = blockIdx.y;
    const size_t k0 = (size_t)ksplit * KPER;

    // ldmatrix per-lane address components (PITCH-byte rows)
    const int aOff = (wm * 64 + ((lane >> 3) & 1) * 8 + (lane & 7)) * PITCH
                   + (lane >> 4) * 16 + kh * 32;                       // + mi*16*PITCH
    const int bOff = (wn * 64 + ((lane >> 4) & 1) * 8 + (lane & 7)) * PITCH
                   + ((lane >> 3) & 1) * 16 + kh * 32;                 // + cb*16*PITCH

    float c[4][8][4];
    #pragma unroll
    for (int mi = 0; mi < 4; ++mi)
        #pragma unroll
        for (int ni = 0; ni < 8; ++ni)
            #pragma unroll
            for (int q = 0; q < 4; ++q) c[mi][ni][q] = 0.f;

    #pragma unroll
    for (int s = 0; s < STAGES - 1; ++s) {
        load_stage(s, s, tid, row_base, k0, smem_base);
        CP_COMMIT();
    }

    for (int it = 0; it < ITERS; ++it) {
        asm volatile("cp.async.wait_group %0;" :: "n"(STAGES - 2) : "memory");
        __syncthreads();

        int nxt = it + STAGES - 1;
        if (nxt < ITERS) load_stage(nxt, nxt & (STAGES - 1), tid, row_base, k0, smem_base);
        CP_COMMIT();

        const uint32_t smA = smem_base + (uint32_t)(it & (STAGES - 1)) * STAGE_BYTES;
        const uint32_t smB = smA + A_TILE_BYTES;

        uint32_t a[4][4], b[4][4];
        #pragma unroll
        for (int mi = 0; mi < 4; ++mi)
            ldsm_x4(a[mi], smA + (uint32_t)(aOff + mi * 16 * PITCH));
        #pragma unroll
        for (int cb = 0; cb < 4; ++cb)
            ldsm_x4(b[cb], smB + (uint32_t)(bOff + cb * 16 * PITCH));
        #pragma unroll
        for (int mi = 0; mi < 4; ++mi) {
            #pragma unroll
            for (int ni = 0; ni < 8; ++ni) {
                mma_f16_16x8x16(c[mi][ni], a[mi][0], a[mi][1], a[mi][2], a[mi][3],
                                b[ni >> 1][(ni & 1) * 2], b[ni >> 1][(ni & 1) * 2 + 1]);
            }
        }
    }

    // ---- epilogue: merge k-half partials through smem, then store ----
    __syncthreads();   // stage buffers are dead; reuse for merge
    const uint32_t pairBase = smem_base + (uint32_t)(wid & 3) * 16384u;
    if (kh == 1) {
        #pragma unroll
        for (int mi = 0; mi < 4; ++mi)
            #pragma unroll
            for (int ni = 0; ni < 8; ++ni) {
                uint32_t off = pairBase + (uint32_t)(((mi * 8 + ni) * 32 + lane) * 16);
                asm volatile("st.shared.v4.b32 [%0], {%1,%2,%3,%4};" :: "r"(off),
                    "r"(__float_as_uint(c[mi][ni][0])), "r"(__float_as_uint(c[mi][ni][1])),
                    "r"(__float_as_uint(c[mi][ni][2])), "r"(__float_as_uint(c[mi][ni][3])) : "memory");
            }
    }
    __syncthreads();
    if (kh == 0) {
        float* P = g_part[ksplit];
        #pragma unroll
        for (int mi = 0; mi < 4; ++mi) {
            const int r0 = row_base + wm * 64 + mi * 16 + g;
            #pragma unroll
            for (int ni = 0; ni < 8; ++ni) {
                uint32_t off = pairBase + (uint32_t)(((mi * 8 + ni) * 32 + lane) * 16);
                float4 p;
                asm volatile("ld.shared.v4.f32 {%0,%1,%2,%3}, [%4];"
                    : "=f"(p.x), "=f"(p.y), "=f"(p.z), "=f"(p.w) : "r"(off));
                const int col = wn * 64 + ni * 8 + 2 * tg;
                float2 lo = make_float2(c[mi][ni][0] + p.x, c[mi][ni][1] + p.y);
                float2 hi = make_float2(c[mi][ni][2] + p.z, c[mi][ni][3] + p.w);
                *reinterpret_cast<float2*>(P + (size_t)r0 * D_OUT + col) = lo;
                *reinterpret_cast<float2*>(P + (size_t)(r0 + 8) * D_OUT + col) = hi;
            }
        }
    }
}

// ================= kernel 4: out = dinv[row] * (part0 + part1) =================
__global__ void reduce_kernel(float* __restrict__ out) {
    int i = blockIdx.x * 256 + threadIdx.x;
    const float4 p0 = reinterpret_cast<const float4*>(g_part[0])[i];
    const float4 p1 = reinterpret_cast<const float4*>(g_part[1])[i];
    int row = (i * 4) >> 7;
    float s = g_dinv[row];
    float4 r;
    r.x = s * (p0.x + p1.x);
    r.y = s * (p0.y + p1.y);
    r.z = s * (p0.z + p1.z);
    r.w = s * (p0.w + p1.w);
    reinterpret_cast<float4*>(out)[i] = r;
}

// ================= launch =================
extern "C" void kernel_launch(void* const* d_in, const int* in_sizes, int n_in,
                              void* d_out, int out_size) {
    const float* values = (const float*)d_in[0];
    const float* A      = (const float*)d_in[1];
    const float* W      = (const float*)d_in[2];
    const float* b      = (const float*)d_in[3];
    float* out = (float*)d_out;

    rowsum_convert_kernel<<<N_NODES, 256>>>(A);
    fc_kernel<<<N_NODES / 32, 256>>>(values, W, b);
    cudaFuncSetAttribute(gemm_kernel, cudaFuncAttributeMaxDynamicSharedMemorySize, GEMM_SMEM);
    gemm_kernel<<<dim3(N_NODES / BM, KSPLIT), 256, GEMM_SMEM>>>();
    reduce_kernel<<<(N_NODES * D_OUT / 4) / 256, 256>>>(out);
}